// round 12
// baseline (speedup 1.0000x reference)
#include <cuda_runtime.h>
#include <cstdint>

#define MBLK    64
#define PDIM    256
#define ROWLEN  16384
#define BK      32
#define NT      24          // K tiles
#define STAGES  3
#define STAGE_BYTES 32768   // A 16KB + B 16KB, 32B-granule swizzle
#define SMEM_BYTES  (STAGES * STAGE_BYTES)   // 98304 -> 2 CTAs/SM

// ---------- tf32 legacy-HMMA GEMM, no weight pre-pass ----------
// Grid (32 mb, 2 nb, 64 i), 128 threads, CTA tile 128x128x32,
// 4 warps 2x2 (64x64), 3-stage cp.async ring, 2 CTAs/SM.
// Both A and W fed raw fp32 (HW tf32-truncation), compensated in epilogue.
// Virtual-k relabel (tg->2tg, tg+4->2tg+1) makes ALL fragment reads LDS.64;
// 32B-granule swizzle keeps them bank-conflict-free.
__global__ void __launch_bounds__(128, 2)
bxd_gemm(const float* __restrict__ x,
         const float* __restrict__ Wd,
         const float* __restrict__ Wu,
         const float* __restrict__ Wl,
         const float* __restrict__ Wtr,
         const float* __restrict__ Wbl,
         float* __restrict__ out) {
    extern __shared__ char smem[];
    uint32_t sbase;
    asm("{ .reg .u64 t; cvta.to.shared.u64 t, %1; cvt.u32.u64 %0, t; }"
        : "=r"(sbase) : "l"(smem));

    const int tid = threadIdx.x;
    const int mb = blockIdx.x;   // batch tile 0..31
    const int nb = blockIdx.y;   // n tile 0..1
    const int i  = blockIdx.z;   // block row 0..63

    const int warp = tid >> 5, lane = tid & 31;
    const int wr = warp >> 1, wc = warp & 1;
    const int g  = lane >> 2, tg = lane & 3;

    // x block-columns per K segment
    int jcol[3];
    jcol[0] = (i + MBLK - 1) & (MBLK - 1);
    jcol[1] = i;
    jcol[2] = (i + 1) & (MBLK - 1);
    // weight segment base pointers (o = x_{j} @ W.T pairing from repack logic)
    const float* pW0 = (i == 0) ? Wtr : Wl + (size_t)(i - 1) * PDIM * PDIM;
    const float* pW1 = Wd + (size_t)i * PDIM * PDIM;
    const float* pW2 = (i == MBLK - 1) ? Wbl : Wu + (size_t)i * PDIM * PDIM;

    // ---- cp.async lanes: lrow 0..15 (+16t), lk4 = 16B chunk 0..7
    const int lrow = tid >> 3;
    const int lk4  = tid & 7;
    // 32B-granule swizzle: granule (lk4>>1) ^ (row&3); 16B half lk4&1
    const int chk  = ((((lk4 >> 1) ^ (lrow & 3)) << 5) | ((lk4 & 1) << 4));
    const float* gA = x + (size_t)(mb * 128 + lrow) * ROWLEN + lk4 * 4;
    const int    bRowG = nb * 128 + lrow;   // weight row (n) base
    const uint32_t sA = sbase + lrow * 128 + chk;
    const uint32_t sB = sA + 16384;

    // ---- fragment base byte offsets (within stage), LDS.64 layout
    // addr = row*128 + ((ks ^ (g&3))<<5) + tg*8
    uint32_t aRow[4][2], bRow[8];
#pragma unroll
    for (int mf = 0; mf < 4; mf++) {
        aRow[mf][0] = (wr * 64 + mf * 16 + g) * 128 + tg * 8;
        aRow[mf][1] = aRow[mf][0] + 8 * 128;
    }
#pragma unroll
    for (int nf = 0; nf < 8; nf++)
        bRow[nf] = 16384 + (wc * 64 + nf * 8 + g) * 128 + tg * 8;

    float acc[4][8][4];
#pragma unroll
    for (int mf = 0; mf < 4; mf++)
#pragma unroll
        for (int nf = 0; nf < 8; nf++)
#pragma unroll
            for (int c = 0; c < 4; c++) acc[mf][nf][c] = 0.0f;

    uint32_t a[2][4][4], b[2][8][2];

    auto issue_A = [&](int kt) {
        const uint32_t st = (kt % STAGES) * STAGE_BYTES;
        const float* a0 = gA + jcol[kt >> 3] * PDIM + (kt & 7) * BK;
#pragma unroll
        for (int t = 0; t < 8; t++)
            asm volatile("cp.async.cg.shared.global [%0], [%1], 16;"
                         :: "r"(sA + st + t * 16 * 128),
                            "l"(a0 + (size_t)t * 16 * ROWLEN));
    };
    auto issue_B = [&](int kt) {
        const uint32_t st = (kt % STAGES) * STAGE_BYTES;
        const float* ws = (kt < 8) ? pW0 : ((kt < 16) ? pW1 : pW2);
        const float* b0 = ws + (size_t)bRowG * PDIM + (kt & 7) * BK + lk4 * 4;
#pragma unroll
        for (int t = 0; t < 8; t++)
            asm volatile("cp.async.cg.shared.global [%0], [%1], 16;"
                         :: "r"(sB + st + t * 16 * 128),
                            "l"(b0 + (size_t)t * 16 * PDIM));
    };

    auto load_frags = [&](uint32_t st, int ks, int buf) {
        const uint32_t gsw = ((uint32_t)(ks ^ (g & 3)) << 5);
        // A: two LDS.64 per mf -> (a0,a2) from row, (a1,a3) from row+8
#pragma unroll
        for (int mf = 0; mf < 4; mf++) {
            asm volatile("ld.shared.v2.b32 {%0, %1}, [%2];"
                         : "=r"(a[buf][mf][0]), "=r"(a[buf][mf][2])
                         : "r"(st + aRow[mf][0] + gsw));
            asm volatile("ld.shared.v2.b32 {%0, %1}, [%2];"
                         : "=r"(a[buf][mf][1]), "=r"(a[buf][mf][3])
                         : "r"(st + aRow[mf][1] + gsw));
        }
        // B: one LDS.64 per nf -> (b0,b1)
#pragma unroll
        for (int nf = 0; nf < 8; nf++)
            asm volatile("ld.shared.v2.b32 {%0, %1}, [%2];"
                         : "=r"(b[buf][nf][0]), "=r"(b[buf][nf][1])
                         : "r"(st + bRow[nf] + gsw));
    };

    issue_A(0); issue_B(0);
    asm volatile("cp.async.commit_group;");
    issue_A(1); issue_B(1);
    asm volatile("cp.async.commit_group;");

    for (int kt = 0; kt < NT; kt++) {
        asm volatile("cp.async.wait_group 1;");
        __syncthreads();

        const uint32_t st = sbase + (kt % STAGES) * STAGE_BYTES;
        const bool pre = (kt + 2 < NT);

        load_frags(st, 0, 0);
#pragma unroll
        for (int ks = 0; ks < 4; ks++) {
            // interleave next-tile global loads under tensor-busy windows
            if (ks == 1 && pre) issue_A(kt + 2);
            if (ks == 2 && pre) issue_B(kt + 2);
            if (ks < 3) load_frags(st, ks + 1, (ks + 1) & 1);
            const int cur = ks & 1;
#pragma unroll
            for (int mf = 0; mf < 4; mf++)
#pragma unroll
                for (int nf = 0; nf < 8; nf++) {
                    float* c = acc[mf][nf];
                    asm volatile(
                        "mma.sync.aligned.m16n8k8.row.col.f32.tf32.tf32.f32 "
                        "{%0,%1,%2,%3}, {%4,%5,%6,%7}, {%8,%9}, {%0,%1,%2,%3};\n"
                        : "+f"(c[0]), "+f"(c[1]), "+f"(c[2]), "+f"(c[3])
                        : "r"(a[cur][mf][0]), "r"(a[cur][mf][1]),
                          "r"(a[cur][mf][2]), "r"(a[cur][mf][3]),
                          "r"(b[cur][nf][0]), "r"(b[cur][nf][1]));
                }
        }
        asm volatile("cp.async.commit_group;");
    }

    // epilogue: compensate mean tf32 truncation of BOTH operands
    // (1 - 2^-11)^2 ~= 1 - 2^-10  ->  multiply by 1 + 2^-10
    const float comp = 1.0009765625f;
    size_t obase = (size_t)(mb * 128 + wr * 64) * ROWLEN
                 + (size_t)i * PDIM + nb * 128 + wc * 64;
#pragma unroll
    for (int mf = 0; mf < 4; mf++) {
#pragma unroll
        for (int nf = 0; nf < 8; nf++) {
            int row = mf * 16 + g;
            int col = nf * 8 + tg * 2;
            float2 v0 = make_float2(acc[mf][nf][0] * comp, acc[mf][nf][1] * comp);
            float2 v1 = make_float2(acc[mf][nf][2] * comp, acc[mf][nf][3] * comp);
            *reinterpret_cast<float2*>(out + obase + (size_t)row * ROWLEN + col) = v0;
            *reinterpret_cast<float2*>(out + obase + (size_t)(row + 8) * ROWLEN + col) = v1;
        }
    }
}

// ---------------- launcher ----------------
extern "C" void kernel_launch(void* const* d_in, const int* in_sizes, int n_in,
                              void* d_out, int out_size) {
    const float* x   = (const float*)d_in[0];
    const float* Wd  = (const float*)d_in[1];
    const float* Wu  = (const float*)d_in[2];
    const float* Wl  = (const float*)d_in[3];
    const float* Wtr = (const float*)d_in[4];
    const float* Wbl = (const float*)d_in[5];
    float* out = (float*)d_out;

    (void)cudaFuncSetAttribute(bxd_gemm,
                               cudaFuncAttributeMaxDynamicSharedMemorySize,
                               SMEM_BYTES);
    bxd_gemm<<<dim3(32, 2, 64), 128, SMEM_BYTES>>>(x, Wd, Wu, Wl, Wtr, Wbl, out);
}